// round 1
// baseline (speedup 1.0000x reference)
#include <cuda_runtime.h>
#include <math.h>

// Problem constants
#define Bsz   64
#define Lseq  512
#define Edim  512
#define Hdim  1024
#define H2    2048   // 2*Hdim

// ---------------------------------------------------------------------------
// Scratch (device globals; no runtime allocation allowed)
// ---------------------------------------------------------------------------
__device__ float g_PRE[32768u * 2048u];   // GEMM outputs (leaf: [Az|Ah], merge: [Az|Ar] then Ah)
__device__ float g_Q  [16384u * 2048u];   // [r*hl | r*hr]
__device__ float g_Zb [16384u * 1024u];   // z gate per pair
__device__ float g_H0 [32768u * 1024u];   // state ping
__device__ float g_H1 [16384u * 1024u];   // state pong
__device__ float g_Wzh[(size_t)Edim * H2];        // [W_z | W_h]
__device__ float g_Uzr[(size_t)H2 * H2];          // [[U_zl,U_rl],[U_zr,U_rr]]
__device__ float g_Uh [(size_t)H2 * Hdim];        // [[U_hl],[U_hr]]
__device__ float g_bz[Hdim], g_br[Hdim], g_bh[Hdim];

// ---------------------------------------------------------------------------
// Weight packing
// ---------------------------------------------------------------------------
__global__ void pack_wzh(const float* __restrict__ Wz, const float* __restrict__ Wh) {
    int idx = blockIdx.x * blockDim.x + threadIdx.x;
    if (idx >= Edim * H2) return;
    int k = idx >> 11, j = idx & (H2 - 1);
    g_Wzh[idx] = (j < Hdim) ? Wz[k * Hdim + j] : Wh[k * Hdim + (j - Hdim)];
}

__global__ void pack_uzr(const float* __restrict__ Uzl, const float* __restrict__ Uzr,
                         const float* __restrict__ Url, const float* __restrict__ Urr) {
    int idx = blockIdx.x * blockDim.x + threadIdx.x;
    if (idx >= H2 * H2) return;
    int k = idx >> 11, j = idx & (H2 - 1);
    int jj = j & (Hdim - 1);
    const float* src;
    if (j < Hdim) src = (k < Hdim) ? (Uzl + (size_t)k * Hdim) : (Uzr + (size_t)(k - Hdim) * Hdim);
    else          src = (k < Hdim) ? (Url + (size_t)k * Hdim) : (Urr + (size_t)(k - Hdim) * Hdim);
    g_Uzr[idx] = src[jj];
}

__global__ void pack_uh(const float* __restrict__ Uhl, const float* __restrict__ Uhr) {
    int idx = blockIdx.x * blockDim.x + threadIdx.x;
    if (idx >= H2 * Hdim) return;
    int k = idx >> 10, j = idx & (Hdim - 1);
    g_Uh[idx] = (k < Hdim) ? Uhl[(size_t)k * Hdim + j] : Uhr[(size_t)(k - Hdim) * Hdim + j];
}

__global__ void pack_bias(const float* bz,  const float* bzl, const float* bzr,
                          const float* br,  const float* brl, const float* brr,
                          const float* bh,  const float* bhl, const float* bhr) {
    int j = blockIdx.x * blockDim.x + threadIdx.x;
    if (j >= Hdim) return;
    g_bz[j] = bz[j] + bzl[j] + bzr[j];
    g_br[j] = br[j] + brl[j] + brr[j];
    g_bh[j] = bh[j] + bhl[j] + bhr[j];
}

// ---------------------------------------------------------------------------
// fp32 GEMM: C[M,N] = A[M,K] @ B[K,N], all row-major.
// lda == K, ldc == N. Optional row gather on A (for the embedding lookup).
// 128x128 block tile, BK=8, 8x8 per thread, 256 threads, float4 everywhere.
// N, K must be multiples of 128/8 (true for all our calls); M guarded.
// ---------------------------------------------------------------------------
template <bool GATHER>
__global__ __launch_bounds__(256)
void sgemm128(const float* __restrict__ A, const float* __restrict__ B,
              float* __restrict__ C, int M, int N, int K,
              const int* __restrict__ rowidx) {
    const int BM = 128, BN = 128, BK = 8;
    __shared__ float As[BK][BM];   // A tile transposed
    __shared__ float Bs[BK][BN];

    const int tid = threadIdx.x;
    const int block_m = blockIdx.y * BM;
    const int block_n = blockIdx.x * BN;

    // Load mappings (one float4 per thread per tile)
    const int a_row = tid >> 1;            // 0..127
    const int a_k4  = (tid & 1) * 4;       // 0 or 4
    const int b_k   = tid >> 5;            // 0..7
    const int b_col = (tid & 31) * 4;      // 0..124

    // Compute mapping
    const int tx = tid & 15;               // col group
    const int ty = tid >> 4;               // row group

    const int g_arow = block_m + a_row;
    const bool arow_ok = (g_arow < M);
    size_t a_src_row;
    if (GATHER) a_src_row = arow_ok ? (size_t)rowidx[g_arow] : 0;
    else        a_src_row = (size_t)(arow_ok ? g_arow : 0);
    const float* a_ptr = A + a_src_row * (size_t)K + a_k4;

    float acc[8][8];
    #pragma unroll
    for (int i = 0; i < 8; i++)
        #pragma unroll
        for (int j = 0; j < 8; j++) acc[i][j] = 0.f;

    for (int k0 = 0; k0 < K; k0 += BK) {
        float4 av = make_float4(0.f, 0.f, 0.f, 0.f);
        if (arow_ok) av = *reinterpret_cast<const float4*>(a_ptr + k0);
        As[a_k4 + 0][a_row] = av.x;
        As[a_k4 + 1][a_row] = av.y;
        As[a_k4 + 2][a_row] = av.z;
        As[a_k4 + 3][a_row] = av.w;

        float4 bv = *reinterpret_cast<const float4*>(
            B + (size_t)(k0 + b_k) * N + block_n + b_col);
        *reinterpret_cast<float4*>(&Bs[b_k][b_col]) = bv;

        __syncthreads();

        #pragma unroll
        for (int k = 0; k < BK; k++) {
            float4 a0 = *reinterpret_cast<const float4*>(&As[k][ty * 8]);
            float4 a1 = *reinterpret_cast<const float4*>(&As[k][ty * 8 + 4]);
            float4 b0 = *reinterpret_cast<const float4*>(&Bs[k][tx * 8]);
            float4 b1 = *reinterpret_cast<const float4*>(&Bs[k][tx * 8 + 4]);
            float a[8] = {a0.x, a0.y, a0.z, a0.w, a1.x, a1.y, a1.z, a1.w};
            float b[8] = {b0.x, b0.y, b0.z, b0.w, b1.x, b1.y, b1.z, b1.w};
            #pragma unroll
            for (int i = 0; i < 8; i++)
                #pragma unroll
                for (int j = 0; j < 8; j++)
                    acc[i][j] += a[i] * b[j];
        }
        __syncthreads();
    }

    #pragma unroll
    for (int i = 0; i < 8; i++) {
        int gm = block_m + ty * 8 + i;
        if (gm >= M) break;
        float* crow = C + (size_t)gm * N + block_n + tx * 8;
        *reinterpret_cast<float4*>(crow)     = make_float4(acc[i][0], acc[i][1], acc[i][2], acc[i][3]);
        *reinterpret_cast<float4*>(crow + 4) = make_float4(acc[i][4], acc[i][5], acc[i][6], acc[i][7]);
    }
}

// ---------------------------------------------------------------------------
// Elementwise kernels
// ---------------------------------------------------------------------------
__device__ __forceinline__ float sigmoidf_(float x) { return 1.f / (1.f + expf(-x)); }

// Leaf: PRE holds [Az | Ah] (stride 2048). h0 = (1-z)*tanh(Ah + bh)
__global__ void leaf_ew(int total) {
    int idx = blockIdx.x * blockDim.x + threadIdx.x;
    if (idx >= total) return;
    int m = idx >> 10, j = idx & (Hdim - 1);
    size_t base = (size_t)m * H2;
    float z  = sigmoidf_(g_PRE[base + j] + g_bz[j]);
    float ht = tanhf(g_PRE[base + Hdim + j] + g_bh[j]);
    g_H0[idx] = (1.f - z) * ht;
}

// Merge stage 1: z/r gates, Q = r * [hl|hr]
__global__ void merge_ew1(const float* __restrict__ X, int total) {
    int idx = blockIdx.x * blockDim.x + threadIdx.x;
    if (idx >= total) return;
    int m = idx >> 10, j = idx & (Hdim - 1);
    size_t base = (size_t)m * H2;
    float z = sigmoidf_(g_PRE[base + j] + g_bz[j]);
    float r = sigmoidf_(g_PRE[base + Hdim + j] + g_br[j]);
    g_Zb[idx] = z;
    g_Q[base + j]        = r * X[base + j];
    g_Q[base + Hdim + j] = r * X[base + Hdim + j];
}

// Merge stage 2: h_out = z*(hl+hr) + (1-z)*tanh(Ah + bh).  Ah in PRE (stride 1024).
__global__ void merge_ew2(const float* __restrict__ X, float* __restrict__ OUT, int total) {
    int idx = blockIdx.x * blockDim.x + threadIdx.x;
    if (idx >= total) return;
    int m = idx >> 10, j = idx & (Hdim - 1);
    size_t base = (size_t)m * H2;
    float z  = g_Zb[idx];
    float ht = tanhf(g_PRE[(size_t)m * Hdim + j] + g_bh[j]);
    float hl = X[base + j];
    float hr = X[base + Hdim + j];
    OUT[idx] = z * (hl + hr) + (1.f - z) * ht;
}

// ---------------------------------------------------------------------------
// Launch
// ---------------------------------------------------------------------------
extern "C" void kernel_launch(void* const* d_in, const int* in_sizes, int n_in,
                              void* d_out, int out_size) {
    const int*   tokens = (const int*)  d_in[0];
    const float* emb    = (const float*)d_in[1];
    const float* W_z  = (const float*)d_in[2];
    const float* b_z  = (const float*)d_in[3];
    const float* U_zl = (const float*)d_in[4];
    const float* b_zl = (const float*)d_in[5];
    const float* U_zr = (const float*)d_in[6];
    const float* b_zr = (const float*)d_in[7];
    // W_r (d_in[8]) / b_r (d_in[9]) feed r; r is needed only at merge levels.
    const float* b_r  = (const float*)d_in[9];
    const float* U_rl = (const float*)d_in[10];
    const float* b_rl = (const float*)d_in[11];
    const float* U_rr = (const float*)d_in[12];
    const float* b_rr = (const float*)d_in[13];
    const float* W_h  = (const float*)d_in[14];
    const float* b_h  = (const float*)d_in[15];
    const float* U_hl = (const float*)d_in[16];
    const float* b_hl = (const float*)d_in[17];
    const float* U_hr = (const float*)d_in[18];
    const float* b_hr = (const float*)d_in[19];

    float *PRE, *Q, *H0, *H1, *Wzh, *Uzr, *Uh;
    cudaGetSymbolAddress((void**)&PRE, g_PRE);
    cudaGetSymbolAddress((void**)&Q,   g_Q);
    cudaGetSymbolAddress((void**)&H0,  g_H0);
    cudaGetSymbolAddress((void**)&H1,  g_H1);
    cudaGetSymbolAddress((void**)&Wzh, g_Wzh);
    cudaGetSymbolAddress((void**)&Uzr, g_Uzr);
    cudaGetSymbolAddress((void**)&Uh,  g_Uh);

    // --- pack weights/biases ---
    pack_wzh<<<(Edim * H2 + 255) / 256, 256>>>(W_z, W_h);
    pack_uzr<<<(H2 * H2 + 255) / 256, 256>>>(U_zl, U_zr, U_rl, U_rr);
    pack_uh <<<(H2 * Hdim + 255) / 256, 256>>>(U_hl, U_hr);
    pack_bias<<<(Hdim + 255) / 256, 256>>>(b_z, b_zl, b_zr, b_r, b_rl, b_rr, b_h, b_hl, b_hr);

    // --- leaf level: word = emb[tokens]; PRE = word @ [W_z|W_h] ---
    {
        const int M = Bsz * Lseq;           // 32768
        dim3 grid(H2 / 128, M / 128);
        sgemm128<true><<<grid, 256>>>(emb, Wzh, PRE, M, H2, Edim, tokens);
        int total = M * Hdim;
        leaf_ew<<<(total + 255) / 256, 256>>>(total);
    }

    // --- merge levels ---
    float* cur = H0;
    for (int n = Lseq; n > 1; n >>= 1) {
        const int M = Bsz * (n / 2);
        float* out = (n == 2) ? (float*)d_out : ((cur == H0) ? H1 : H0);
        const int total = M * Hdim;
        const int gy = (M + 127) / 128;

        dim3 g1(H2 / 128, gy);
        sgemm128<false><<<g1, 256>>>(cur, Uzr, PRE, M, H2, H2, nullptr);
        merge_ew1<<<(total + 255) / 256, 256>>>(cur, total);

        dim3 g2(Hdim / 128, gy);
        sgemm128<false><<<g2, 256>>>(Q, Uh, PRE, M, Hdim, H2, nullptr);
        merge_ew2<<<(total + 255) / 256, 256>>>(cur, out, total);

        cur = out;
    }
}

// round 3
// speedup vs baseline: 2.8087x; 2.8087x over previous
#include <cuda_runtime.h>
#include <cuda_bf16.h>
#include <math.h>
#include <cstdint>

#define Bsz   64
#define Lseq  512
#define Edim  512
#define Hdim  1024
#define H2    2048

// ---------------------------------------------------------------------------
// Scratch (device globals; no runtime allocation allowed)
// ---------------------------------------------------------------------------
__device__ float g_PRE[32768u * 2048u];   // GEMM outputs
__device__ float g_Zb [16384u * 1024u];   // z gate per pair
__device__ float g_H0 [32768u * 1024u];   // state ping (fp32)
__device__ float g_H1 [16384u * 1024u];   // state pong (fp32)
// bf16 hi/lo split activations
__device__ __nv_bfloat16 g_Wh [32768u * 512u];
__device__ __nv_bfloat16 g_Wl [32768u * 512u];
__device__ __nv_bfloat16 g_H0h[32768u * 1024u];
__device__ __nv_bfloat16 g_H0l[32768u * 1024u];
__device__ __nv_bfloat16 g_H1h[16384u * 1024u];
__device__ __nv_bfloat16 g_H1l[16384u * 1024u];
__device__ __nv_bfloat16 g_Qh [16384u * 2048u];
__device__ __nv_bfloat16 g_Ql [16384u * 2048u];
// Transposed [N,K] weights split to bf16 hi/lo
__device__ __nv_bfloat16 g_WzhT_h[(size_t)H2 * Edim];
__device__ __nv_bfloat16 g_WzhT_l[(size_t)H2 * Edim];
__device__ __nv_bfloat16 g_UzrT_h[(size_t)H2 * H2];
__device__ __nv_bfloat16 g_UzrT_l[(size_t)H2 * H2];
__device__ __nv_bfloat16 g_UhT_h [(size_t)Hdim * H2];
__device__ __nv_bfloat16 g_UhT_l [(size_t)Hdim * H2];
__device__ float g_bz[Hdim], g_br[Hdim], g_bh[Hdim];

// ---------------------------------------------------------------------------
// Helpers
// ---------------------------------------------------------------------------
__device__ __forceinline__ uint32_t smem_u32(const void* p) {
    uint32_t a;
    asm("{ .reg .u64 t; cvta.to.shared.u64 t, %1; cvt.u32.u64 %0, t; }" : "=r"(a) : "l"(p));
    return a;
}
// SW64 swizzle for 64-byte rows (8-row atom, conflict-free ldmatrix/cp.async)
__device__ __forceinline__ uint32_t swz64(uint32_t row, uint32_t byte) {
    return row * 64u + (byte ^ (((row >> 1) & 3u) << 4));
}
__device__ __forceinline__ void cp16(uint32_t dst, const void* src, uint32_t srcsize) {
    asm volatile("cp.async.cg.shared.global [%0], [%1], 16, %2;"
                 :: "r"(dst), "l"(src), "r"(srcsize));
}
__device__ __forceinline__ void ldsm4(uint32_t* r, uint32_t addr) {
    asm volatile("ldmatrix.sync.aligned.m8n8.x4.shared.b16 {%0,%1,%2,%3}, [%4];"
                 : "=r"(r[0]), "=r"(r[1]), "=r"(r[2]), "=r"(r[3]) : "r"(addr));
}
__device__ __forceinline__ void mma16816(float* d, const uint32_t* a, uint32_t b0, uint32_t b1) {
    asm volatile("mma.sync.aligned.m16n8k16.row.col.f32.bf16.bf16.f32 "
                 "{%0,%1,%2,%3}, {%4,%5,%6,%7}, {%8,%9}, {%0,%1,%2,%3};"
                 : "+f"(d[0]), "+f"(d[1]), "+f"(d[2]), "+f"(d[3])
                 : "r"(a[0]), "r"(a[1]), "r"(a[2]), "r"(a[3]), "r"(b0), "r"(b1));
}
__device__ __forceinline__ void split_pair(float v, __nv_bfloat16& h, __nv_bfloat16& l) {
    h = __float2bfloat16_rn(v);
    l = __float2bfloat16_rn(v - __bfloat162float(h));
}

// ---------------------------------------------------------------------------
// Weight packing: transposed [N,K], split into bf16 hi/lo
// ---------------------------------------------------------------------------
__global__ void pack_wzhT(const float* __restrict__ Wz, const float* __restrict__ Wh) {
    int idx = blockIdx.x * blockDim.x + threadIdx.x;
    if (idx >= H2 * Edim) return;
    int j = idx / Edim, k = idx - j * Edim;
    float v = (j < Hdim) ? Wz[k * Hdim + j] : Wh[k * Hdim + (j - Hdim)];
    split_pair(v, g_WzhT_h[idx], g_WzhT_l[idx]);
}

__global__ void pack_uzrT(const float* __restrict__ Uzl, const float* __restrict__ Uzr,
                          const float* __restrict__ Url, const float* __restrict__ Urr) {
    int idx = blockIdx.x * blockDim.x + threadIdx.x;
    if (idx >= H2 * H2) return;
    int j = idx >> 11, k = idx & (H2 - 1);
    int jj = j & (Hdim - 1), kk = k & (Hdim - 1);
    float v;
    if (j < Hdim) v = (k < Hdim) ? Uzl[(size_t)k * Hdim + j]  : Uzr[(size_t)kk * Hdim + j];
    else          v = (k < Hdim) ? Url[(size_t)k * Hdim + jj] : Urr[(size_t)kk * Hdim + jj];
    split_pair(v, g_UzrT_h[idx], g_UzrT_l[idx]);
}

__global__ void pack_uhT(const float* __restrict__ Uhl, const float* __restrict__ Uhr) {
    int idx = blockIdx.x * blockDim.x + threadIdx.x;
    if (idx >= Hdim * H2) return;
    int j = idx >> 11, k = idx & (H2 - 1);
    float v = (k < Hdim) ? Uhl[(size_t)k * Hdim + j] : Uhr[(size_t)(k - Hdim) * Hdim + j];
    split_pair(v, g_UhT_h[idx], g_UhT_l[idx]);
}

__global__ void pack_bias(const float* bz, const float* bzl, const float* bzr,
                          const float* br, const float* brl, const float* brr,
                          const float* bh, const float* bhl, const float* bhr) {
    int j = blockIdx.x * blockDim.x + threadIdx.x;
    if (j >= Hdim) return;
    g_bz[j] = bz[j] + bzl[j] + bzr[j];
    g_br[j] = br[j] + brl[j] + brr[j];
    g_bh[j] = bh[j] + bhl[j] + bhr[j];
}

// Gather + split the embedding rows: word = emb[tokens] -> (Wh, Wl)
__global__ void gather_split(const int* __restrict__ tokens, const float* __restrict__ emb) {
    int idx = blockIdx.x * blockDim.x + threadIdx.x;
    if (idx >= Bsz * Lseq * Edim) return;
    int m = idx >> 9, k = idx & (Edim - 1);
    float v = emb[(size_t)tokens[m] * Edim + k];
    split_pair(v, g_Wh[idx], g_Wl[idx]);
}

// ---------------------------------------------------------------------------
// bf16-split GEMM via mma.sync: C[M,N] = (Ah+Al)[M,K] @ (Bh+Bl)[N,K]^T
// (3 passes: AhBh + AhBl + AlBh, fp32 accumulate)
// CTA 128x128, 8 warps (2x4, warp tile 64x32), BK=32, cp.async double buffer.
// ---------------------------------------------------------------------------
#define BKE 32
#define STAGE_BYTES 32768
#define OFF_AH 0
#define OFF_AL 8192
#define OFF_BH 16384
#define OFF_BL 24576
#define GEMM_SMEM (2 * STAGE_BYTES)

__global__ __launch_bounds__(256)
void mmagemm(const __nv_bfloat16* __restrict__ Ah, const __nv_bfloat16* __restrict__ Al,
             const __nv_bfloat16* __restrict__ Bh, const __nv_bfloat16* __restrict__ Bl,
             float* __restrict__ C, int M, int N, int K) {
    extern __shared__ char smem[];
    const uint32_t sb = smem_u32(smem);
    const int tid = threadIdx.x, wid = tid >> 5, lane = tid & 31;
    const int bm = blockIdx.y * 128, bn = blockIdx.x * 128;

    // cp.async mapping: thread -> (row, k-half); two 16B chunks per array
    const int ld_row = tid >> 1;
    const uint32_t ld_kb = (uint32_t)(tid & 1) * 32u;     // byte offset in 64B row
    const int a_gr = bm + ld_row;
    const uint32_t a_sz = (a_gr < M) ? 16u : 0u;
    const int a_cl = (a_gr < M) ? a_gr : 0;
    const __nv_bfloat16* ah_src = Ah + (size_t)a_cl * K;
    const __nv_bfloat16* al_src = Al + (size_t)a_cl * K;
    const __nv_bfloat16* bh_src = Bh + (size_t)(bn + ld_row) * K;
    const __nv_bfloat16* bl_src = Bl + (size_t)(bn + ld_row) * K;
    const uint32_t dst0 = swz64((uint32_t)ld_row, ld_kb);
    const uint32_t dst1 = swz64((uint32_t)ld_row, ld_kb + 16u);
    const int ld_ke = (int)(ld_kb >> 1);                  // elem offset (bf16)

    // ldmatrix lane mappings
    const uint32_t a_lr = (uint32_t)(lane & 15);
    const uint32_t a_lb = (uint32_t)(lane >> 4) * 16u;
    const uint32_t b_lr = (uint32_t)((lane & 7) + ((lane >> 4) << 3));
    const uint32_t b_lb = (uint32_t)((lane >> 3) & 1) * 16u;
    const uint32_t wm = (uint32_t)(wid >> 2) * 64u;
    const uint32_t wn = (uint32_t)(wid & 3) * 32u;

    float acc[4][4][4];
    #pragma unroll
    for (int i = 0; i < 4; i++)
        #pragma unroll
        for (int j = 0; j < 4; j++)
            #pragma unroll
            for (int q = 0; q < 4; q++) acc[i][j][q] = 0.f;

    const int NC = K / BKE;

    // stage loader
    auto load_stage = [&](int s, int c) {
        const uint32_t base = sb + (uint32_t)s * STAGE_BYTES;
        const int ke = c * BKE + ld_ke;
        cp16(base + OFF_AH + dst0, ah_src + ke,     a_sz);
        cp16(base + OFF_AH + dst1, ah_src + ke + 8, a_sz);
        cp16(base + OFF_AL + dst0, al_src + ke,     a_sz);
        cp16(base + OFF_AL + dst1, al_src + ke + 8, a_sz);
        cp16(base + OFF_BH + dst0, bh_src + ke,     16u);
        cp16(base + OFF_BH + dst1, bh_src + ke + 8, 16u);
        cp16(base + OFF_BL + dst0, bl_src + ke,     16u);
        cp16(base + OFF_BL + dst1, bl_src + ke + 8, 16u);
        asm volatile("cp.async.commit_group;");
    };

    load_stage(0, 0);

    for (int c = 0; c < NC; c++) {
        if (c + 1 < NC) {
            load_stage((c + 1) & 1, c + 1);
            asm volatile("cp.async.wait_group 1;");
        } else {
            asm volatile("cp.async.wait_group 0;");
        }
        __syncthreads();

        const uint32_t base = sb + (uint32_t)(c & 1) * STAGE_BYTES;
        #pragma unroll
        for (int ks = 0; ks < 2; ks++) {
            const uint32_t kb = (uint32_t)ks * 32u;
            uint32_t a[16], bh[8], bl[8];
            #pragma unroll
            for (int p = 0; p < 2; p++) {
                ldsm4(&bh[p * 4], base + OFF_BH + swz64(wn + p * 16u + b_lr, kb + b_lb));
                ldsm4(&bl[p * 4], base + OFF_BL + swz64(wn + p * 16u + b_lr, kb + b_lb));
            }
            #pragma unroll
            for (int mi = 0; mi < 4; mi++)
                ldsm4(&a[mi * 4], base + OFF_AH + swz64(wm + mi * 16u + a_lr, kb + a_lb));
            // Ah * Bh
            #pragma unroll
            for (int mi = 0; mi < 4; mi++)
                #pragma unroll
                for (int ni = 0; ni < 4; ni++)
                    mma16816(acc[mi][ni], &a[mi * 4],
                             bh[(ni >> 1) * 4 + (ni & 1) * 2], bh[(ni >> 1) * 4 + (ni & 1) * 2 + 1]);
            // Ah * Bl
            #pragma unroll
            for (int mi = 0; mi < 4; mi++)
                #pragma unroll
                for (int ni = 0; ni < 4; ni++)
                    mma16816(acc[mi][ni], &a[mi * 4],
                             bl[(ni >> 1) * 4 + (ni & 1) * 2], bl[(ni >> 1) * 4 + (ni & 1) * 2 + 1]);
            // Al * Bh
            #pragma unroll
            for (int mi = 0; mi < 4; mi++)
                ldsm4(&a[mi * 4], base + OFF_AL + swz64(wm + mi * 16u + a_lr, kb + a_lb));
            #pragma unroll
            for (int mi = 0; mi < 4; mi++)
                #pragma unroll
                for (int ni = 0; ni < 4; ni++)
                    mma16816(acc[mi][ni], &a[mi * 4],
                             bh[(ni >> 1) * 4 + (ni & 1) * 2], bh[(ni >> 1) * 4 + (ni & 1) * 2 + 1]);
        }
        __syncthreads();
    }

    // Epilogue
    const int er = lane >> 2, ec = (lane & 3) * 2;
    #pragma unroll
    for (int mi = 0; mi < 4; mi++) {
        #pragma unroll
        for (int ni = 0; ni < 4; ni++) {
            const int r0 = bm + (int)wm + mi * 16 + er;
            const int col = bn + (int)wn + ni * 8 + ec;
            if (r0 < M)
                *reinterpret_cast<float2*>(C + (size_t)r0 * N + col)
                    = make_float2(acc[mi][ni][0], acc[mi][ni][1]);
            if (r0 + 8 < M)
                *reinterpret_cast<float2*>(C + (size_t)(r0 + 8) * N + col)
                    = make_float2(acc[mi][ni][2], acc[mi][ni][3]);
        }
    }
}

// ---------------------------------------------------------------------------
// Elementwise kernels
// ---------------------------------------------------------------------------
__device__ __forceinline__ float sigmoidf_(float x) { return 1.f / (1.f + expf(-x)); }

// Leaf: PRE = [Az|Ah] (stride 2048). h0 = (1-z)*tanh(Ah+bh); also split h0.
__global__ void leaf_ew(int total) {
    int idx = blockIdx.x * blockDim.x + threadIdx.x;
    if (idx >= total) return;
    int m = idx >> 10, j = idx & (Hdim - 1);
    size_t base = (size_t)m * H2;
    float z  = sigmoidf_(g_PRE[base + j] + g_bz[j]);
    float ht = tanhf(g_PRE[base + Hdim + j] + g_bh[j]);
    float h = (1.f - z) * ht;
    g_H0[idx] = h;
    split_pair(h, g_H0h[idx], g_H0l[idx]);
}

// Merge stage 1: z/r gates; Q = r*[hl|hr] written directly as bf16 hi/lo
__global__ void merge_ew1(const float* __restrict__ X, int total) {
    int idx = blockIdx.x * blockDim.x + threadIdx.x;
    if (idx >= total) return;
    int m = idx >> 10, j = idx & (Hdim - 1);
    size_t base = (size_t)m * H2;
    float z = sigmoidf_(g_PRE[base + j] + g_bz[j]);
    float r = sigmoidf_(g_PRE[base + Hdim + j] + g_br[j]);
    g_Zb[idx] = z;
    split_pair(r * X[base + j],        g_Qh[base + j],        g_Ql[base + j]);
    split_pair(r * X[base + Hdim + j], g_Qh[base + Hdim + j], g_Ql[base + Hdim + j]);
}

// Merge stage 2: h = z*(hl+hr) + (1-z)*tanh(Ah+bh); optionally split for next level
__global__ void merge_ew2(const float* __restrict__ X, float* __restrict__ OUT,
                          __nv_bfloat16* __restrict__ OUTh, __nv_bfloat16* __restrict__ OUTl,
                          int total, int do_split) {
    int idx = blockIdx.x * blockDim.x + threadIdx.x;
    if (idx >= total) return;
    int m = idx >> 10, j = idx & (Hdim - 1);
    size_t base = (size_t)m * H2;
    float z  = g_Zb[idx];
    float ht = tanhf(g_PRE[(size_t)m * Hdim + j] + g_bh[j]);
    float h = z * (X[base + j] + X[base + Hdim + j]) + (1.f - z) * ht;
    OUT[idx] = h;
    if (do_split) split_pair(h, OUTh[idx], OUTl[idx]);
}

// ---------------------------------------------------------------------------
// Launch
// ---------------------------------------------------------------------------
extern "C" void kernel_launch(void* const* d_in, const int* in_sizes, int n_in,
                              void* d_out, int out_size) {
    const int*   tokens = (const int*)  d_in[0];
    const float* emb    = (const float*)d_in[1];
    const float* W_z  = (const float*)d_in[2];
    const float* b_z  = (const float*)d_in[3];
    const float* U_zl = (const float*)d_in[4];
    const float* b_zl = (const float*)d_in[5];
    const float* U_zr = (const float*)d_in[6];
    const float* b_zr = (const float*)d_in[7];
    const float* b_r  = (const float*)d_in[9];
    const float* U_rl = (const float*)d_in[10];
    const float* b_rl = (const float*)d_in[11];
    const float* U_rr = (const float*)d_in[12];
    const float* b_rr = (const float*)d_in[13];
    const float* W_h  = (const float*)d_in[14];
    const float* b_h  = (const float*)d_in[15];
    const float* U_hl = (const float*)d_in[16];
    const float* b_hl = (const float*)d_in[17];
    const float* U_hr = (const float*)d_in[18];
    const float* b_hr = (const float*)d_in[19];

    float *PRE, *H0, *H1;
    __nv_bfloat16 *Wh, *Wl, *H0h, *H0l, *H1h, *H1l, *Qh, *Ql;
    __nv_bfloat16 *WzhTh, *WzhTl, *UzrTh, *UzrTl, *UhTh, *UhTl;
    cudaGetSymbolAddress((void**)&PRE, g_PRE);
    cudaGetSymbolAddress((void**)&H0,  g_H0);
    cudaGetSymbolAddress((void**)&H1,  g_H1);
    cudaGetSymbolAddress((void**)&Wh,  g_Wh);
    cudaGetSymbolAddress((void**)&Wl,  g_Wl);
    cudaGetSymbolAddress((void**)&H0h, g_H0h);
    cudaGetSymbolAddress((void**)&H0l, g_H0l);
    cudaGetSymbolAddress((void**)&H1h, g_H1h);
    cudaGetSymbolAddress((void**)&H1l, g_H1l);
    cudaGetSymbolAddress((void**)&Qh,  g_Qh);
    cudaGetSymbolAddress((void**)&Ql,  g_Ql);
    cudaGetSymbolAddress((void**)&WzhTh, g_WzhT_h);
    cudaGetSymbolAddress((void**)&WzhTl, g_WzhT_l);
    cudaGetSymbolAddress((void**)&UzrTh, g_UzrT_h);
    cudaGetSymbolAddress((void**)&UzrTl, g_UzrT_l);
    cudaGetSymbolAddress((void**)&UhTh,  g_UhT_h);
    cudaGetSymbolAddress((void**)&UhTl,  g_UhT_l);

    cudaFuncSetAttribute(mmagemm, cudaFuncAttributeMaxDynamicSharedMemorySize, GEMM_SMEM);

    // --- pack weights/biases ---
    pack_wzhT<<<(H2 * Edim + 255) / 256, 256>>>(W_z, W_h);
    pack_uzrT<<<(H2 * H2 + 255) / 256, 256>>>(U_zl, U_zr, U_rl, U_rr);
    pack_uhT <<<(Hdim * H2 + 255) / 256, 256>>>(U_hl, U_hr);
    pack_bias<<<(Hdim + 255) / 256, 256>>>(b_z, b_zl, b_zr, b_r, b_rl, b_rr, b_h, b_hl, b_hr);

    // --- leaf: word split, then PRE = word @ [W_z|W_h] ---
    {
        const int M = Bsz * Lseq;           // 32768
        gather_split<<<(M * Edim + 255) / 256, 256>>>(tokens, emb);
        dim3 grid(H2 / 128, M / 128);
        mmagemm<<<grid, 256, GEMM_SMEM>>>(Wh, Wl, WzhTh, WzhTl, PRE, M, H2, Edim);
        int total = M * Hdim;
        leaf_ew<<<(total + 255) / 256, 256>>>(total);
    }

    // --- merge levels ---
    float* cur = H0;
    __nv_bfloat16 *curh = H0h, *curl = H0l;
    for (int n = Lseq; n > 1; n >>= 1) {
        const int M = Bsz * (n / 2);
        const bool last = (n == 2);
        float* out = last ? (float*)d_out : ((cur == H0) ? H1 : H0);
        __nv_bfloat16* outh = (cur == H0) ? H1h : H0h;
        __nv_bfloat16* outl = (cur == H0) ? H1l : H0l;
        const int total = M * Hdim;
        const int gy = (M + 127) / 128;

        dim3 g1(H2 / 128, gy);
        mmagemm<<<g1, 256, GEMM_SMEM>>>(curh, curl, UzrTh, UzrTl, PRE, M, H2, H2);
        merge_ew1<<<(total + 255) / 256, 256>>>(cur, total);

        dim3 g2(Hdim / 128, gy);
        mmagemm<<<g2, 256, GEMM_SMEM>>>(Qh, Ql, UhTh, UhTl, PRE, M, Hdim, H2);
        merge_ew2<<<(total + 255) / 256, 256>>>(cur, out, outh, outl, total, last ? 0 : 1);

        cur = out; curh = outh; curl = outl;
    }
}